// round 16
// baseline (speedup 1.0000x reference)
#include <cuda_runtime.h>
#include <cuda_bf16.h>
#include <math.h>
#include <stdint.h>

// Problem constants
#define NGRAPH 1024
#define EPG 1024
#define E_TOTAL (NGRAPH * EPG)
#define HID 256
#define BN_COUNT 65536.0f
#define EPS 1e-5f

typedef unsigned long long ull;

union F4U { float4 f; ull u[2]; float s[4]; };
union F2U { float2 f; ull u; float s[2]; };

__device__ __forceinline__ ull splat2(float x) {
    ull r; asm("mov.b64 %0, {%1, %1};" : "=l"(r) : "f"(x)); return r;
}
__device__ __forceinline__ ull fma2(ull a, ull b, ull c) {
    ull d; asm("fma.rn.f32x2 %0, %1, %2, %3;" : "=l"(d) : "l"(a), "l"(b), "l"(c)); return d;
}
__device__ __forceinline__ float2 un2(ull v) {
    float2 f; asm("mov.b64 {%0, %1}, %2;" : "=f"(f.x), "=f"(f.y) : "l"(v)); return f;
}

// Scratch (device globals; no allocation allowed)
__device__ float g_buf1[NGRAPH * 64 * 64];    // 16 MB
__device__ float g_buf2[NGRAPH * 64 * 64];    // 16 MB (also GEMM1 partials)
__device__ float g_act1[NGRAPH * HID];
__device__ float g_stats[384];                // 3 BNs x (64 sum + 64 sumsq)
__device__ float g_wt[2 * 12288];             // transposed conv weights [r][o]

// ---------------------------------------------------------------------------
// Transpose conv weights into [r=k*64+i][o] layout, both convs; zero stats.
__global__ void prep_wt_kernel(const float* __restrict__ c2w,
                               const float* __restrict__ c3w,
                               float* __restrict__ wt,
                               float* __restrict__ st) {
    int idx = blockIdx.x * 256 + threadIdx.x;     // 0..24575
    if (idx < 384) st[idx] = 0.f;
    int j = idx;
    const float* cw = c2w;
    float* o = wt;
    if (j >= 12288) { j -= 12288; cw = c3w; o = wt + 12288; }
    int r = j >> 6, oo = j & 63;
    int k = r >> 6, i = r & 63;
    o[j] = cw[oo * 192 + i * 3 + k];
}

// ---------------------------------------------------------------------------
// EdgeConv via linearity: sum_e relu(h_e) @ w2 = (sum_e relu(h_e)) @ w2.
// Phase 1: per-edge 4-dim hidden, shared atomic accumulate into hsum[node][4].
// Phase 2: expand 4->64 features per node, write + BN1 stats.
__global__ void edgeconv_kernel(const float* __restrict__ x,
                                const int* __restrict__ ei,
                                const float* __restrict__ w1,
                                const float* __restrict__ b1,
                                const float* __restrict__ w2,
                                const float* __restrict__ b2,
                                float* __restrict__ out,
                                float* __restrict__ stg) {
    __shared__ float sx[64];
    __shared__ float sw2[4][64];
    __shared__ float sb2v[64];
    __shared__ float sw1v[8];
    __shared__ float sb1v[4];
    __shared__ __align__(16) float hsum[256];   // [node][4]
    __shared__ float scnt[64];
    __shared__ float2 ps2[8][32], pq2[8][32];

    int g = blockIdx.x, tid = threadIdx.x;
    const int* srcp = ei + g * EPG;
    const int* dstp = ei + E_TOTAL + g * EPG;

    if (tid < 64) {
        sx[tid] = x[g * 64 + tid];
        sb2v[tid] = b2[tid];
        sw2[0][tid] = w2[tid];
        sw2[1][tid] = w2[64 + tid];
        sw2[2][tid] = w2[128 + tid];
        sw2[3][tid] = w2[192 + tid];
        scnt[tid] = 0.f;
    }
    if (tid < 8) sw1v[tid] = w1[tid];
    if (tid < 4) sb1v[tid] = b1[tid];
    hsum[tid] = 0.f;
    __syncthreads();

    float wa0 = sw1v[0], wa1 = sw1v[1], wa2 = sw1v[2], wa3 = sw1v[3];
    float wb0 = sw1v[4], wb1 = sw1v[5], wb2 = sw1v[6], wb3 = sw1v[7];
    float c0 = sb1v[0], c1 = sb1v[1], c2 = sb1v[2], c3 = sb1v[3];
#pragma unroll
    for (int t = 0; t < 4; t++) {
        int e = tid + t * 256;
        int s = srcp[e] & 63;
        int d = dstp[e] & 63;
        float xi = sx[d];
        float xd = sx[s] - xi;
        float h0 = fmaxf(fmaf(xd, wb0, fmaf(xi, wa0, c0)), 0.f);
        float h1 = fmaxf(fmaf(xd, wb1, fmaf(xi, wa1, c1)), 0.f);
        float h2 = fmaxf(fmaf(xd, wb2, fmaf(xi, wa2, c2)), 0.f);
        float h3 = fmaxf(fmaf(xd, wb3, fmaf(xi, wa3, c3)), 0.f);
        atomicAdd(&hsum[d * 4 + 0], h0);
        atomicAdd(&hsum[d * 4 + 1], h1);
        atomicAdd(&hsum[d * 4 + 2], h2);
        atomicAdd(&hsum[d * 4 + 3], h3);
        atomicAdd(&scnt[d], 1.f);
    }
    __syncthreads();

    // Expand: thread = feature pair f2, node d strided by 8 (warp-uniform d)
    int f2 = tid & 31, dq = tid >> 5;
    F2U u0p, u1p, u2p, u3p, bbp;
    u0p.f = *(const float2*)&sw2[0][f2 * 2];
    u1p.f = *(const float2*)&sw2[1][f2 * 2];
    u2p.f = *(const float2*)&sw2[2][f2 * 2];
    u3p.f = *(const float2*)&sw2[3][f2 * 2];
    bbp.f = *(const float2*)&sb2v[f2 * 2];
    float* out_g = out + g * 4096;
    float2 Sacc = make_float2(0.f, 0.f), Qacc = make_float2(0.f, 0.f);
#pragma unroll
    for (int d = dq; d < 64; d += 8) {
        F4U h; h.f = *(const float4*)&hsum[d * 4];
        float n = scnt[d];
        F2U a0;
        a0.f.x = bbp.f.x * n; a0.f.y = bbp.f.y * n;
        ull acc0 = a0.u;
        acc0 = fma2(splat2(h.s[0]), u0p.u, acc0);
        acc0 = fma2(splat2(h.s[1]), u1p.u, acc0);
        acc0 = fma2(splat2(h.s[2]), u2p.u, acc0);
        acc0 = fma2(splat2(h.s[3]), u3p.u, acc0);
        float2 c = un2(acc0);
        *(float2*)&out_g[d * 64 + f2 * 2] = c;
        Sacc.x += c.x; Sacc.y += c.y;
        Qacc.x += c.x * c.x; Qacc.y += c.y * c.y;
    }
    ps2[dq][f2] = Sacc;
    pq2[dq][f2] = Qacc;
    __syncthreads();
    if (tid < 32) {
        float sx_ = 0.f, sy_ = 0.f;
#pragma unroll
        for (int w = 0; w < 8; w++) { sx_ += ps2[w][tid].x; sy_ += ps2[w][tid].y; }
        atomicAdd(&stg[2 * tid], sx_);
        atomicAdd(&stg[2 * tid + 1], sy_);
    } else if (tid < 64) {
        int f = tid - 32;
        float qx = 0.f, qy = 0.f;
#pragma unroll
        for (int w = 0; w < 8; w++) { qx += pq2[w][f].x; qy += pq2[w][f].y; }
        atomicAdd(&stg[64 + 2 * f], qx);
        atomicAdd(&stg[64 + 2 * f + 1], qy);
    }
}

// ---------------------------------------------------------------------------
// Fused BN(+ReLU) + Conv1d(64,64,3,pad=1), all-taps-per-i f32x2 kernel.
// GSTRIDE = 4368 (== 16 mod 32 banks): both graph halves of a warp hit
// disjoint banks -> conflict-free B loads. 256 threads, 2 graphs/CTA.
#define GSTRIDE 4368
#define CONV_SMEM ((2 * GSTRIDE + 12288 + 128) * 4)

#define CTAP(wA, wB, sA, sB, sC, sD) \
    acc[0][0] = fma2(wA.u[0], sA, acc[0][0]); \
    acc[1][0] = fma2(wA.u[1], sA, acc[1][0]); \
    acc[2][0] = fma2(wB.u[0], sA, acc[2][0]); \
    acc[3][0] = fma2(wB.u[1], sA, acc[3][0]); \
    acc[0][1] = fma2(wA.u[0], sB, acc[0][1]); \
    acc[1][1] = fma2(wA.u[1], sB, acc[1][1]); \
    acc[2][1] = fma2(wB.u[0], sB, acc[2][1]); \
    acc[3][1] = fma2(wB.u[1], sB, acc[3][1]); \
    acc[0][2] = fma2(wA.u[0], sC, acc[0][2]); \
    acc[1][2] = fma2(wA.u[1], sC, acc[1][2]); \
    acc[2][2] = fma2(wB.u[0], sC, acc[2][2]); \
    acc[3][2] = fma2(wB.u[1], sC, acc[3][2]); \
    acc[0][3] = fma2(wA.u[0], sD, acc[0][3]); \
    acc[1][3] = fma2(wA.u[1], sD, acc[1][3]); \
    acc[2][3] = fma2(wB.u[0], sD, acc[2][3]); \
    acc[3][3] = fma2(wB.u[1], sD, acc[3][3]);

template <bool TIN>
__global__ __launch_bounds__(256, 2)
void conv8_kernel(const float* __restrict__ in,
                  const float* __restrict__ st_in,
                  const float* __restrict__ gamma,
                  const float* __restrict__ beta,
                  const float* __restrict__ wt,
                  const float* __restrict__ cb,
                  float* __restrict__ out,
                  float* __restrict__ st_out) {
    extern __shared__ float smem[];
    float* Sg = smem;                 // [2][GSTRIDE]: per graph [64 ch][68], halo 0/65
    float* Ws = smem + 2 * GSTRIDE;   // [192][64]  (r = k*64+i)
    float* Ssc = Ws + 12288;          // [64]
    float* Ssh = Ssc + 64;            // [64]

    int tid = threadIdx.x;
    int g0 = blockIdx.x * 2;

    {
        const float4* w4 = (const float4*)wt;
        float4* d4 = (float4*)Ws;
#pragma unroll
        for (int t = 0; t < 12; t++) d4[tid + t * 256] = w4[tid + t * 256];
    }
    if (tid < 64) {
        float mean = st_in[tid] * (1.f / BN_COUNT);
        float var = st_in[64 + tid] * (1.f / BN_COUNT) - mean * mean;
        float inv = rsqrtf(var + EPS);
        float sc = gamma[tid] * inv;
        Ssc[tid] = sc;
        Ssh[tid] = beta[tid] - mean * sc;
    }
    if (tid < 128) {   // zero halos
        int g = tid >> 6, i = tid & 63;
        Sg[g * GSTRIDE + i * 68] = 0.f;
        Sg[g * GSTRIDE + i * 68 + 65] = 0.f;
    }
    __syncthreads();

    // Stage BN+ReLU input into Sg[g][i*68 + l + 1]
    const float4* in4 = (const float4*)(in + (size_t)g0 * 4096);
#pragma unroll
    for (int t = 0; t < 8; t++) {
        int idx4 = tid + t * 256;               // 0..2047
        int g = idx4 >> 10;
        int e = (idx4 & 1023) * 4;
        float4 v = in4[idx4];
        if (TIN) {
            int l = e >> 6, i0 = e & 63;
            float* b = &Sg[g * GSTRIDE + l + 1];
            b[(i0 + 0) * 68] = fmaxf(fmaf(v.x, Ssc[i0],     Ssh[i0]),     0.f);
            b[(i0 + 1) * 68] = fmaxf(fmaf(v.y, Ssc[i0 + 1], Ssh[i0 + 1]), 0.f);
            b[(i0 + 2) * 68] = fmaxf(fmaf(v.z, Ssc[i0 + 2], Ssh[i0 + 2]), 0.f);
            b[(i0 + 3) * 68] = fmaxf(fmaf(v.w, Ssc[i0 + 3], Ssh[i0 + 3]), 0.f);
        } else {
            int i = e >> 6, l0 = e & 63;
            float sc = Ssc[i], sh = Ssh[i];
            float* b = &Sg[g * GSTRIDE + i * 68 + l0 + 1];
            b[0] = fmaxf(fmaf(v.x, sc, sh), 0.f);
            b[1] = fmaxf(fmaf(v.y, sc, sh), 0.f);
            b[2] = fmaxf(fmaf(v.z, sc, sh), 0.f);
            b[3] = fmaxf(fmaf(v.w, sc, sh), 0.f);
        }
    }
    __syncthreads();

    int ot = tid >> 5, lt = tid & 31;
    int o8 = ot * 8;
    int gg = lt >> 4, l4 = (lt & 15) * 4;
    ull acc[4][4];                     // [o-pair][l]
    {
        F4U b0; b0.f = *(const float4*)&cb[o8];
        F4U b1; b1.f = *(const float4*)&cb[o8 + 4];
#pragma unroll
        for (int jj = 0; jj < 4; jj++) {
            acc[0][jj] = b0.u[0]; acc[1][jj] = b0.u[1];
            acc[2][jj] = b1.u[0]; acc[3][jj] = b1.u[1];
        }
    }

    const float* Bg = &Sg[gg * GSTRIDE + l4];
    const float* W0 = &Ws[o8];
    const float* W1 = &Ws[4096 + o8];
    const float* W2 = &Ws[8192 + o8];
#pragma unroll 2
    for (int i = 0; i < 64; i++) {
        F4U bv; bv.f = *(const float4*)Bg;        // B slots l4..l4+3
        F2U be; be.f = *(const float2*)(Bg + 4);  // slots l4+4, l4+5
        ull s0 = splat2(bv.s[0]), s1 = splat2(bv.s[1]);
        ull s2 = splat2(bv.s[2]), s3 = splat2(bv.s[3]);
        ull s4 = splat2(be.s[0]), s5 = splat2(be.s[1]);
        {
            F4U wv0; wv0.f = *(const float4*)W0;
            F4U wv1; wv1.f = *(const float4*)(W0 + 4);
            CTAP(wv0, wv1, s0, s1, s2, s3)
        }
        {
            F4U wv0; wv0.f = *(const float4*)W1;
            F4U wv1; wv1.f = *(const float4*)(W1 + 4);
            CTAP(wv0, wv1, s1, s2, s3, s4)
        }
        {
            F4U wv0; wv0.f = *(const float4*)W2;
            F4U wv1; wv1.f = *(const float4*)(W2 + 4);
            CTAP(wv0, wv1, s2, s3, s4, s5)
        }
        Bg += 68; W0 += 64; W1 += 64; W2 += 64;
    }

    // Epilogue: vectorized chan-major store + BN stats
    float* og = out + (size_t)(g0 + gg) * 4096;
#pragma unroll
    for (int q = 0; q < 4; q++) {
        int o = o8 + 2 * q;
        float2 v0 = un2(acc[q][0]), v1 = un2(acc[q][1]);
        float2 v2 = un2(acc[q][2]), v3 = un2(acc[q][3]);
        float4 r0 = make_float4(v0.x, v1.x, v2.x, v3.x);
        float4 r1 = make_float4(v0.y, v1.y, v2.y, v3.y);
        *(float4*)&og[o * 64 + l4] = r0;
        *(float4*)&og[(o + 1) * 64 + l4] = r1;
        float s0 = r0.x + r0.y + r0.z + r0.w;
        float q0 = r0.x * r0.x + r0.y * r0.y + r0.z * r0.z + r0.w * r0.w;
        float s1 = r1.x + r1.y + r1.z + r1.w;
        float q1 = r1.x * r1.x + r1.y * r1.y + r1.z * r1.z + r1.w * r1.w;
#pragma unroll
        for (int w = 1; w < 32; w <<= 1) {
            s0 += __shfl_xor_sync(0xffffffffu, s0, w);
            q0 += __shfl_xor_sync(0xffffffffu, q0, w);
            s1 += __shfl_xor_sync(0xffffffffu, s1, w);
            q1 += __shfl_xor_sync(0xffffffffu, q1, w);
        }
        if (lt == 0) {
            atomicAdd(&st_out[o], s0);
            atomicAdd(&st_out[64 + o], q0);
            atomicAdd(&st_out[o + 1], s1);
            atomicAdd(&st_out[64 + o + 1], q1);
        }
    }
}

// ---------------------------------------------------------------------------
// 8x8 register-blocked f32x2 GEMM for GEMM1 with fused BN3+ReLU on A.
// Conflict-free B loads: thread owns n = nt*4 + 64j (lanes 16B-contiguous).
__global__ __launch_bounds__(128)
void gemm8_kernel(const float* __restrict__ A,
                  const float* __restrict__ W,
                  const float* __restrict__ st,
                  const float* __restrict__ gamma,
                  const float* __restrict__ beta,
                  float* __restrict__ C,
                  int M, int N, int K, int KS) {
    __shared__ float As[16][68];    // [kk][m]
    __shared__ float Bs[16][128];   // [kk][n]
    __shared__ float Fsc[64], Fsh[64];
    int bm = blockIdx.x * 64, bn = blockIdx.y * 128;
    int zi = blockIdx.z;
    int kbeg = zi * KS;
    int tid = threadIdx.x;
    if (tid < 64) {
        float mean = st[tid] * (1.f / BN_COUNT);
        float var = st[64 + tid] * (1.f / BN_COUNT) - mean * mean;
        float inv = rsqrtf(var + EPS);
        float sc = gamma[tid] * inv;
        Fsc[tid] = sc;
        Fsh[tid] = beta[tid] - mean * sc;
    }
    __syncthreads();
    int mt = tid >> 4, nt = tid & 15;
    int m8 = mt * 8, n4 = nt * 4;
    ull acc[8][4];
#pragma unroll
    for (int i = 0; i < 8; i++)
#pragma unroll
        for (int j = 0; j < 4; j++) acc[i][j] = 0ull;

    for (int k0 = kbeg; k0 < kbeg + KS; k0 += 16) {
#pragma unroll
        for (int t = 0; t < 2; t++) {
            int fi = tid + t * 128;            // 0..255 float4 in 64x16 A tile
            int r = fi >> 2, c4 = (fi & 3) * 4;
            float4 v = *(const float4*)&A[(size_t)(bm + r) * K + k0 + c4];
            int ch = (k0 + c4) >> 6;
            float sc = Fsc[ch], sh = Fsh[ch];
            As[c4 + 0][r] = fmaxf(fmaf(v.x, sc, sh), 0.f);
            As[c4 + 1][r] = fmaxf(fmaf(v.y, sc, sh), 0.f);
            As[c4 + 2][r] = fmaxf(fmaf(v.z, sc, sh), 0.f);
            As[c4 + 3][r] = fmaxf(fmaf(v.w, sc, sh), 0.f);
        }
#pragma unroll
        for (int t = 0; t < 4; t++) {
            int fi = tid + t * 128;            // 0..511 float4 in 16x128 B tile
            int r = fi >> 5, c = (fi & 31) * 4;
            *(float4*)&Bs[r][c] = *(const float4*)&W[(size_t)(k0 + r) * N + bn + c];
        }
        __syncthreads();
#pragma unroll
        for (int kk = 0; kk < 16; kk++) {
            F4U a0; a0.f = *(const float4*)&As[kk][m8];
            F4U a1; a1.f = *(const float4*)&As[kk][m8 + 4];
            F4U b0; b0.f = *(const float4*)&Bs[kk][n4];
            F4U b1; b1.f = *(const float4*)&Bs[kk][n4 + 64];
            float am[8] = {a0.s[0], a0.s[1], a0.s[2], a0.s[3],
                           a1.s[0], a1.s[1], a1.s[2], a1.s[3]};
#pragma unroll
            for (int i = 0; i < 8; i++) {
                ull as_ = splat2(am[i]);
                acc[i][0] = fma2(as_, b0.u[0], acc[i][0]);
                acc[i][1] = fma2(as_, b0.u[1], acc[i][1]);
                acc[i][2] = fma2(as_, b1.u[0], acc[i][2]);
                acc[i][3] = fma2(as_, b1.u[1], acc[i][3]);
            }
        }
        __syncthreads();
    }
    float* Co = C + (size_t)zi * M * N;
#pragma unroll
    for (int i = 0; i < 8; i++) {
        F4U c0, c1;
        c0.u[0] = acc[i][0]; c0.u[1] = acc[i][1];
        c1.u[0] = acc[i][2]; c1.u[1] = acc[i][3];
        float* row = &Co[(size_t)(bm + m8 + i) * N + bn];
        *(float4*)&row[n4] = c0.f;
        *(float4*)&row[n4 + 64] = c1.f;
    }
}

// Combine 16 K-split partials + bias + relu. 256 blocks x 256 threads x float4.
__global__ void combine16_relu_kernel(const float* __restrict__ p,
                                      const float* __restrict__ bias,
                                      float* __restrict__ out) {
    int i4 = blockIdx.x * 256 + threadIdx.x;
    int e = i4 * 4;
    int n = e & 255;
    float4 acc = *(const float4*)&bias[n];
#pragma unroll
    for (int z = 0; z < 16; z++) {
        float4 v = *(const float4*)&p[(size_t)z * 262144 + e];
        acc.x += v.x; acc.y += v.y; acc.z += v.z; acc.w += v.w;
    }
    acc.x = fmaxf(acc.x, 0.f);
    acc.y = fmaxf(acc.y, 0.f);
    acc.z = fmaxf(acc.z, 0.f);
    acc.w = fmaxf(acc.w, 0.f);
    *(float4*)&out[e] = acc;
}

// ---------------------------------------------------------------------------
// Fused tail: act2 = relu(act1@wm2+bm2); act3 = relu(act2@wm3+bm3);
// logits = act3@wp+bp; log_softmax. 128 blocks x 8 graphs, 128 threads.
// Thread = (g = tid>>4, nt = tid&15); outputs n = nt*4 + 64j (conflict-free).
#define TAIL_SMEM ((8 * 256 + 8 * 256 + 32 * 256 + 128) * 4)

__device__ __forceinline__ void tail_gemm(const float* __restrict__ Asrc,
                                          float* __restrict__ Cdst,
                                          float* __restrict__ Sw,
                                          const float* __restrict__ W,
                                          const float* __restrict__ bias,
                                          int gt, int nt, int tid) {
    ull acc[4][2];
#pragma unroll
    for (int j = 0; j < 4; j++) { acc[j][0] = 0ull; acc[j][1] = 0ull; }
    for (int chunk = 0; chunk < 8; chunk++) {
        int k0 = chunk * 32;
        const float4* w4 = (const float4*)(W + k0 * 256);
        float4* d4 = (float4*)Sw;
#pragma unroll
        for (int t = 0; t < 16; t++) d4[tid + t * 128] = w4[tid + t * 128];
        __syncthreads();
        const float* ar = Asrc + gt * 256 + k0;
#pragma unroll 4
        for (int kk = 0; kk < 32; kk++) {
            ull as_ = splat2(ar[kk]);
            const float* wr = &Sw[kk * 256 + nt * 4];
            F4U b0; b0.f = *(const float4*)wr;
            F4U b1; b1.f = *(const float4*)(wr + 64);
            F4U b2; b2.f = *(const float4*)(wr + 128);
            F4U b3; b3.f = *(const float4*)(wr + 192);
            acc[0][0] = fma2(as_, b0.u[0], acc[0][0]);
            acc[0][1] = fma2(as_, b0.u[1], acc[0][1]);
            acc[1][0] = fma2(as_, b1.u[0], acc[1][0]);
            acc[1][1] = fma2(as_, b1.u[1], acc[1][1]);
            acc[2][0] = fma2(as_, b2.u[0], acc[2][0]);
            acc[2][1] = fma2(as_, b2.u[1], acc[2][1]);
            acc[3][0] = fma2(as_, b3.u[0], acc[3][0]);
            acc[3][1] = fma2(as_, b3.u[1], acc[3][1]);
        }
        __syncthreads();
    }
#pragma unroll
    for (int j = 0; j < 4; j++) {
        F4U c; c.u[0] = acc[j][0]; c.u[1] = acc[j][1];
        F4U b; b.f = *(const float4*)&bias[nt * 4 + 64 * j];
        c.s[0] = fmaxf(c.s[0] + b.s[0], 0.f);
        c.s[1] = fmaxf(c.s[1] + b.s[1], 0.f);
        c.s[2] = fmaxf(c.s[2] + b.s[2], 0.f);
        c.s[3] = fmaxf(c.s[3] + b.s[3], 0.f);
        *(float4*)&Cdst[gt * 256 + nt * 4 + 64 * j] = c.f;
    }
    __syncthreads();
}

__global__ __launch_bounds__(128)
void tail_kernel(const float* __restrict__ act,
                 const float* __restrict__ wm2, const float* __restrict__ bm2,
                 const float* __restrict__ wm3, const float* __restrict__ bm3,
                 const float* __restrict__ wp, const float* __restrict__ bp,
                 float* __restrict__ outp) {
    extern __shared__ float tsm[];
    float* Sa = tsm;              // [8][256]
    float* Sc = tsm + 2048;       // [8][256]
    float* Sw = tsm + 4096;       // [32][256] weight chunk / wp
    float* sl = tsm + 4096 + 8192;// [128]
    int tid = threadIdx.x;
    int g0 = blockIdx.x * 8;
    {
        const float4* a4 = (const float4*)(act + (size_t)g0 * 256);
        float4* d4 = (float4*)Sa;
#pragma unroll
        for (int t = 0; t < 4; t++) d4[tid + t * 128] = a4[tid + t * 128];
    }
    __syncthreads();
    int gt = tid >> 4, nt = tid & 15;
    tail_gemm(Sa, Sc, Sw, wm2, bm2, gt, nt, tid);
    tail_gemm(Sc, Sa, Sw, wm3, bm3, gt, nt, tid);
    // load wp [256][16] into Sw
    {
        const float4* p4 = (const float4*)wp;
        float4* d4 = (float4*)Sw;
#pragma unroll
        for (int t = 0; t < 8; t++) d4[tid + t * 128] = p4[tid + t * 128];
    }
    __syncthreads();
    float acc = bp[nt];
    const float* ar = &Sa[gt * 256];
#pragma unroll 8
    for (int k = 0; k < 256; k++) acc = fmaf(ar[k], Sw[k * 16 + nt], acc);
    sl[tid] = acc;
    __syncthreads();
    int base = tid & ~15;
    float m = -1e30f;
#pragma unroll
    for (int j = 0; j < 16; j++) m = fmaxf(m, sl[base + j]);
    float s = 0.f;
#pragma unroll
    for (int j = 0; j < 16; j++) s += expf(sl[base + j] - m);
    outp[(g0 + gt) * 16 + nt] = acc - m - logf(s);
}

// ---------------------------------------------------------------------------
extern "C" void kernel_launch(void* const* d_in, const int* in_sizes, int n_in,
                              void* d_out, int out_size) {
    const float* x   = (const float*)d_in[0];
    const int*   ei  = (const int*)d_in[1];
    const float* w1  = (const float*)d_in[2];
    const float* b1  = (const float*)d_in[3];
    const float* w2  = (const float*)d_in[4];
    const float* b2  = (const float*)d_in[5];
    const float* c2w = (const float*)d_in[6];
    const float* c2b = (const float*)d_in[7];
    const float* c3w = (const float*)d_in[8];
    const float* c3b = (const float*)d_in[9];
    const float* g1  = (const float*)d_in[10];
    const float* be1 = (const float*)d_in[11];
    const float* g2  = (const float*)d_in[12];
    const float* be2 = (const float*)d_in[13];
    const float* g3  = (const float*)d_in[14];
    const float* be3 = (const float*)d_in[15];
    const float* wm1 = (const float*)d_in[16];
    const float* bm1 = (const float*)d_in[17];
    const float* wm2 = (const float*)d_in[18];
    const float* bm2 = (const float*)d_in[19];
    const float* wm3 = (const float*)d_in[20];
    const float* bm3 = (const float*)d_in[21];
    const float* wp  = (const float*)d_in[22];
    const float* bp  = (const float*)d_in[23];
    float* out = (float*)d_out;

    float *buf1, *buf2, *act1, *st, *wt;
    cudaGetSymbolAddress((void**)&buf1, g_buf1);
    cudaGetSymbolAddress((void**)&buf2, g_buf2);
    cudaGetSymbolAddress((void**)&act1, g_act1);
    cudaGetSymbolAddress((void**)&st, g_stats);
    cudaGetSymbolAddress((void**)&wt, g_wt);

    cudaFuncSetAttribute(conv8_kernel<true>,
                         cudaFuncAttributeMaxDynamicSharedMemorySize, CONV_SMEM);
    cudaFuncSetAttribute(conv8_kernel<false>,
                         cudaFuncAttributeMaxDynamicSharedMemorySize, CONV_SMEM);
    cudaFuncSetAttribute(tail_kernel,
                         cudaFuncAttributeMaxDynamicSharedMemorySize, TAIL_SMEM);

    prep_wt_kernel<<<96, 256>>>(c2w, c3w, wt, st);
    edgeconv_kernel<<<NGRAPH, 256>>>(x, ei, w1, b1, w2, b2, buf1, st);
    conv8_kernel<true><<<512, 256, CONV_SMEM>>>(buf1, st, g1, be1, wt, c2b, buf2, st + 128);
    conv8_kernel<false><<<512, 256, CONV_SMEM>>>(buf2, st + 128, g2, be2, wt + 12288, c3b, buf1, st + 256);
    gemm8_kernel<<<dim3(16, 2, 16), 128>>>(buf1, wm1, st + 256, g3, be3, buf2, 1024, 256, 4096, 256);
    combine16_relu_kernel<<<256, 256>>>(buf2, bm1, act1);
    tail_kernel<<<128, 128, TAIL_SMEM>>>(act1, wm2, bm2, wm3, bm3, wp, bp, out);
}

// round 17
// speedup vs baseline: 1.6411x; 1.6411x over previous
#include <cuda_runtime.h>
#include <cuda_bf16.h>
#include <math.h>
#include <stdint.h>

// Problem constants
#define NGRAPH 1024
#define EPG 1024
#define E_TOTAL (NGRAPH * EPG)
#define HID 256
#define BN_COUNT 65536.0f
#define EPS 1e-5f

typedef unsigned long long ull;

union F4U { float4 f; ull u[2]; float s[4]; };
union F2U { float2 f; ull u; float s[2]; };

__device__ __forceinline__ ull splat2(float x) {
    ull r; asm("mov.b64 %0, {%1, %1};" : "=l"(r) : "f"(x)); return r;
}
__device__ __forceinline__ ull fma2(ull a, ull b, ull c) {
    ull d; asm("fma.rn.f32x2 %0, %1, %2, %3;" : "=l"(d) : "l"(a), "l"(b), "l"(c)); return d;
}
__device__ __forceinline__ float2 un2(ull v) {
    float2 f; asm("mov.b64 {%0, %1}, %2;" : "=f"(f.x), "=f"(f.y) : "l"(v)); return f;
}

// Scratch (device globals; no allocation allowed)
__device__ float g_buf1[NGRAPH * 64 * 64];    // 16 MB
__device__ float g_buf2[NGRAPH * 64 * 64];    // 16 MB (also GEMM1 partials)
__device__ float g_act1[NGRAPH * HID];
__device__ float g_act2[NGRAPH * HID];
__device__ float g_stats[384];                // 3 BNs x (64 sum + 64 sumsq)
__device__ float g_wt[2 * 12288];             // transposed conv weights [r][o]

// ---------------------------------------------------------------------------
// Transpose conv weights into [r=k*64+i][o] layout, both convs; zero stats.
__global__ void prep_wt_kernel(const float* __restrict__ c2w,
                               const float* __restrict__ c3w,
                               float* __restrict__ wt,
                               float* __restrict__ st) {
    int idx = blockIdx.x * 256 + threadIdx.x;     // 0..24575
    if (idx < 384) st[idx] = 0.f;
    int j = idx;
    const float* cw = c2w;
    float* o = wt;
    if (j >= 12288) { j -= 12288; cw = c3w; o = wt + 12288; }
    int r = j >> 6, oo = j & 63;
    int k = r >> 6, i = r & 63;
    o[j] = cw[oo * 192 + i * 3 + k];
}

// ---------------------------------------------------------------------------
// EdgeConv: one block per graph, counting-sort edges by dst, f32x2 accumulate.
// out layout: [(g*64 + node)*64 + feat]. Also accumulates BN1 stats (stg).
__global__ void edgeconv_kernel(const float* __restrict__ x,
                                const int* __restrict__ ei,
                                const float* __restrict__ w1,
                                const float* __restrict__ b1,
                                const float* __restrict__ w2,
                                const float* __restrict__ b2,
                                float* __restrict__ out,
                                float* __restrict__ stg) {
    __shared__ float sx[64];
    __shared__ float sw2[4][64];
    __shared__ float sb2v[64];
    __shared__ float sw1v[8];
    __shared__ float sb1v[4];
    __shared__ int s_src[EPG];
    __shared__ int s_d[EPG];
    __shared__ float shh[EPG * 4];
    __shared__ int cnt[64], off[64], pos[64];
    __shared__ float2 ps2[8][32], pq2[8][32];

    int g = blockIdx.x, tid = threadIdx.x;
    const int* srcp = ei + g * EPG;
    const int* dstp = ei + E_TOTAL + g * EPG;

    if (tid < 64) {
        sx[tid] = x[g * 64 + tid];
        sb2v[tid] = b2[tid];
        sw2[0][tid] = w2[tid];
        sw2[1][tid] = w2[64 + tid];
        sw2[2][tid] = w2[128 + tid];
        sw2[3][tid] = w2[192 + tid];
        cnt[tid] = 0;
    }
    if (tid < 8) sw1v[tid] = w1[tid];
    if (tid < 4) sb1v[tid] = b1[tid];
    __syncthreads();

    for (int e = tid; e < EPG; e += 256) {
        int s = srcp[e] & 63;
        int d = dstp[e] & 63;
        s_src[e] = s;
        s_d[e] = d;
        atomicAdd(&cnt[d], 1);
    }
    __syncthreads();
    if (tid == 0) {
        int a = 0;
        for (int i = 0; i < 64; i++) { off[i] = a; a += cnt[i]; }
    }
    __syncthreads();
    if (tid < 64) pos[tid] = off[tid];
    __syncthreads();

    float wa0 = sw1v[0], wa1 = sw1v[1], wa2 = sw1v[2], wa3 = sw1v[3];
    float wb0 = sw1v[4], wb1 = sw1v[5], wb2 = sw1v[6], wb3 = sw1v[7];
    float c0 = sb1v[0], c1 = sb1v[1], c2 = sb1v[2], c3 = sb1v[3];
    for (int e = tid; e < EPG; e += 256) {
        int d = s_d[e];
        float xi = sx[d];
        float xd = sx[s_src[e]] - xi;
        float h0 = fmaxf(fmaf(xd, wb0, fmaf(xi, wa0, c0)), 0.f);
        float h1 = fmaxf(fmaf(xd, wb1, fmaf(xi, wa1, c1)), 0.f);
        float h2 = fmaxf(fmaf(xd, wb2, fmaf(xi, wa2, c2)), 0.f);
        float h3 = fmaxf(fmaf(xd, wb3, fmaf(xi, wa3, c3)), 0.f);
        int p = atomicAdd(&pos[d], 1);
        *(float4*)&shh[p * 4] = make_float4(h0, h1, h2, h3);
    }
    __syncthreads();

    // f32x2 accumulate: thread = feature pair f2, d strided by 8 (warp-uniform d)
    int f2 = tid & 31, dq = tid >> 5;
    F2U u0p, u1p, u2p, u3p, bbp;
    u0p.f = *(const float2*)&sw2[0][f2 * 2];
    u1p.f = *(const float2*)&sw2[1][f2 * 2];
    u2p.f = *(const float2*)&sw2[2][f2 * 2];
    u3p.f = *(const float2*)&sw2[3][f2 * 2];
    bbp.f = *(const float2*)&sb2v[f2 * 2];
    float* out_g = out + g * 4096;
    float2 Sacc = make_float2(0.f, 0.f), Qacc = make_float2(0.f, 0.f);
    for (int d = dq; d < 64; d += 8) {
        int st0 = off[d], en = st0 + cnt[d];
        float n = (float)(en - st0);
        F2U a0, a1;
        a0.f.x = bbp.f.x * n; a0.f.y = bbp.f.y * n;
        a1.f.x = 0.f; a1.f.y = 0.f;
        ull acc0 = a0.u, acc1 = a1.u;
        for (int e = st0; e < en; e++) {
            float4 h = *(const float4*)&shh[e * 4];
            acc0 = fma2(splat2(h.x), u0p.u, acc0);
            acc1 = fma2(splat2(h.y), u1p.u, acc1);
            acc0 = fma2(splat2(h.z), u2p.u, acc0);
            acc1 = fma2(splat2(h.w), u3p.u, acc1);
        }
        float2 v0 = un2(acc0), v1 = un2(acc1);
        float2 c;
        c.x = v0.x + v1.x;
        c.y = v0.y + v1.y;
        *(float2*)&out_g[d * 64 + f2 * 2] = c;
        Sacc.x += c.x; Sacc.y += c.y;
        Qacc.x += c.x * c.x; Qacc.y += c.y * c.y;
    }
    ps2[dq][f2] = Sacc;
    pq2[dq][f2] = Qacc;
    __syncthreads();
    if (tid < 32) {
        float sx_ = 0.f, sy_ = 0.f;
#pragma unroll
        for (int w = 0; w < 8; w++) { sx_ += ps2[w][tid].x; sy_ += ps2[w][tid].y; }
        atomicAdd(&stg[2 * tid], sx_);
        atomicAdd(&stg[2 * tid + 1], sy_);
    } else if (tid < 64) {
        int f = tid - 32;
        float qx = 0.f, qy = 0.f;
#pragma unroll
        for (int w = 0; w < 8; w++) { qx += pq2[w][f].x; qy += pq2[w][f].y; }
        atomicAdd(&stg[64 + 2 * f], qx);
        atomicAdd(&stg[64 + 2 * f + 1], qy);
    }
}

// ---------------------------------------------------------------------------
// Fused BN(+ReLU) + Conv1d(64,64,3,pad=1), all-taps-per-i f32x2 kernel.
// R14 layout (GSTRIDE 4352). 256 threads, 2 graphs per CTA, weights in smem.
#define GSTRIDE 4352
#define CONV_SMEM ((2 * GSTRIDE + 12288 + 128) * 4)

#define CTAP(wA, wB, sA, sB, sC, sD) \
    acc[0][0] = fma2(wA.u[0], sA, acc[0][0]); \
    acc[1][0] = fma2(wA.u[1], sA, acc[1][0]); \
    acc[2][0] = fma2(wB.u[0], sA, acc[2][0]); \
    acc[3][0] = fma2(wB.u[1], sA, acc[3][0]); \
    acc[0][1] = fma2(wA.u[0], sB, acc[0][1]); \
    acc[1][1] = fma2(wA.u[1], sB, acc[1][1]); \
    acc[2][1] = fma2(wB.u[0], sB, acc[2][1]); \
    acc[3][1] = fma2(wB.u[1], sB, acc[3][1]); \
    acc[0][2] = fma2(wA.u[0], sC, acc[0][2]); \
    acc[1][2] = fma2(wA.u[1], sC, acc[1][2]); \
    acc[2][2] = fma2(wB.u[0], sC, acc[2][2]); \
    acc[3][2] = fma2(wB.u[1], sC, acc[3][2]); \
    acc[0][3] = fma2(wA.u[0], sD, acc[0][3]); \
    acc[1][3] = fma2(wA.u[1], sD, acc[1][3]); \
    acc[2][3] = fma2(wB.u[0], sD, acc[2][3]); \
    acc[3][3] = fma2(wB.u[1], sD, acc[3][3]);

template <bool TIN>
__global__ __launch_bounds__(256, 2)
void conv8_kernel(const float* __restrict__ in,
                  const float* __restrict__ st_in,
                  const float* __restrict__ gamma,
                  const float* __restrict__ beta,
                  const float* __restrict__ wt,
                  const float* __restrict__ cb,
                  float* __restrict__ out,
                  float* __restrict__ st_out) {
    extern __shared__ float smem[];
    float* Sg = smem;                 // [2][GSTRIDE]: per graph [64 ch][68], halo 0/65
    float* Ws = smem + 2 * GSTRIDE;   // [192][64]  (r = k*64+i)
    float* Ssc = Ws + 12288;          // [64]
    float* Ssh = Ssc + 64;            // [64]

    int tid = threadIdx.x;
    int g0 = blockIdx.x * 2;

    {
        const float4* w4 = (const float4*)wt;
        float4* d4 = (float4*)Ws;
#pragma unroll
        for (int t = 0; t < 12; t++) d4[tid + t * 256] = w4[tid + t * 256];
    }
    if (tid < 64) {
        float mean = st_in[tid] * (1.f / BN_COUNT);
        float var = st_in[64 + tid] * (1.f / BN_COUNT) - mean * mean;
        float inv = rsqrtf(var + EPS);
        float sc = gamma[tid] * inv;
        Ssc[tid] = sc;
        Ssh[tid] = beta[tid] - mean * sc;
    }
    if (tid < 128) {   // zero halos
        int g = tid >> 6, i = tid & 63;
        Sg[g * GSTRIDE + i * 68] = 0.f;
        Sg[g * GSTRIDE + i * 68 + 65] = 0.f;
    }
    __syncthreads();

    // Stage BN+ReLU input into Sg[g][i*68 + l + 1]
    const float4* in4 = (const float4*)(in + (size_t)g0 * 4096);
#pragma unroll
    for (int t = 0; t < 8; t++) {
        int idx4 = tid + t * 256;               // 0..2047
        int g = idx4 >> 10;
        int e = (idx4 & 1023) * 4;
        float4 v = in4[idx4];
        if (TIN) {
            int l = e >> 6, i0 = e & 63;
            float* b = &Sg[g * GSTRIDE + l + 1];
            b[(i0 + 0) * 68] = fmaxf(fmaf(v.x, Ssc[i0],     Ssh[i0]),     0.f);
            b[(i0 + 1) * 68] = fmaxf(fmaf(v.y, Ssc[i0 + 1], Ssh[i0 + 1]), 0.f);
            b[(i0 + 2) * 68] = fmaxf(fmaf(v.z, Ssc[i0 + 2], Ssh[i0 + 2]), 0.f);
            b[(i0 + 3) * 68] = fmaxf(fmaf(v.w, Ssc[i0 + 3], Ssh[i0 + 3]), 0.f);
        } else {
            int i = e >> 6, l0 = e & 63;
            float sc = Ssc[i], sh = Ssh[i];
            float* b = &Sg[g * GSTRIDE + i * 68 + l0 + 1];
            b[0] = fmaxf(fmaf(v.x, sc, sh), 0.f);
            b[1] = fmaxf(fmaf(v.y, sc, sh), 0.f);
            b[2] = fmaxf(fmaf(v.z, sc, sh), 0.f);
            b[3] = fmaxf(fmaf(v.w, sc, sh), 0.f);
        }
    }
    __syncthreads();

    int ot = tid >> 5, lt = tid & 31;
    int o8 = ot * 8;
    int gg = lt >> 4, l4 = (lt & 15) * 4;
    ull acc[4][4];                     // [o-pair][l]
    {
        F4U b0; b0.f = *(const float4*)&cb[o8];
        F4U b1; b1.f = *(const float4*)&cb[o8 + 4];
#pragma unroll
        for (int jj = 0; jj < 4; jj++) {
            acc[0][jj] = b0.u[0]; acc[1][jj] = b0.u[1];
            acc[2][jj] = b1.u[0]; acc[3][jj] = b1.u[1];
        }
    }

    const float* Bg = &Sg[gg * GSTRIDE + l4];
    const float* W0 = &Ws[o8];
    const float* W1 = &Ws[4096 + o8];
    const float* W2 = &Ws[8192 + o8];
#pragma unroll 2
    for (int i = 0; i < 64; i++) {
        F4U bv; bv.f = *(const float4*)Bg;        // B slots l4..l4+3
        F2U be; be.f = *(const float2*)(Bg + 4);  // slots l4+4, l4+5
        ull s0 = splat2(bv.s[0]), s1 = splat2(bv.s[1]);
        ull s2 = splat2(bv.s[2]), s3 = splat2(bv.s[3]);
        ull s4 = splat2(be.s[0]), s5 = splat2(be.s[1]);
        {
            F4U wv0; wv0.f = *(const float4*)W0;
            F4U wv1; wv1.f = *(const float4*)(W0 + 4);
            CTAP(wv0, wv1, s0, s1, s2, s3)
        }
        {
            F4U wv0; wv0.f = *(const float4*)W1;
            F4U wv1; wv1.f = *(const float4*)(W1 + 4);
            CTAP(wv0, wv1, s1, s2, s3, s4)
        }
        {
            F4U wv0; wv0.f = *(const float4*)W2;
            F4U wv1; wv1.f = *(const float4*)(W2 + 4);
            CTAP(wv0, wv1, s2, s3, s4, s5)
        }
        Bg += 68; W0 += 64; W1 += 64; W2 += 64;
    }

    // Epilogue: vectorized chan-major store + BN stats
    float* og = out + (size_t)(g0 + gg) * 4096;
#pragma unroll
    for (int q = 0; q < 4; q++) {
        int o = o8 + 2 * q;
        float2 v0 = un2(acc[q][0]), v1 = un2(acc[q][1]);
        float2 v2 = un2(acc[q][2]), v3 = un2(acc[q][3]);
        float4 r0 = make_float4(v0.x, v1.x, v2.x, v3.x);
        float4 r1 = make_float4(v0.y, v1.y, v2.y, v3.y);
        *(float4*)&og[o * 64 + l4] = r0;
        *(float4*)&og[(o + 1) * 64 + l4] = r1;
        float s0 = r0.x + r0.y + r0.z + r0.w;
        float q0 = r0.x * r0.x + r0.y * r0.y + r0.z * r0.z + r0.w * r0.w;
        float s1 = r1.x + r1.y + r1.z + r1.w;
        float q1 = r1.x * r1.x + r1.y * r1.y + r1.z * r1.z + r1.w * r1.w;
#pragma unroll
        for (int w = 1; w < 32; w <<= 1) {
            s0 += __shfl_xor_sync(0xffffffffu, s0, w);
            q0 += __shfl_xor_sync(0xffffffffu, q0, w);
            s1 += __shfl_xor_sync(0xffffffffu, s1, w);
            q1 += __shfl_xor_sync(0xffffffffu, q1, w);
        }
        if (lt == 0) {
            atomicAdd(&st_out[o], s0);
            atomicAdd(&st_out[64 + o], q0);
            atomicAdd(&st_out[o + 1], s1);
            atomicAdd(&st_out[64 + o + 1], q1);
        }
    }
}

// ---------------------------------------------------------------------------
// 8x8 register-blocked f32x2 GEMM for GEMM1 with fused BN3+ReLU on A.
// Conflict-free B loads: thread owns n = nt*4 + 64j (lanes 16B-contiguous).
__global__ __launch_bounds__(128)
void gemm8_kernel(const float* __restrict__ A,
                  const float* __restrict__ W,
                  const float* __restrict__ st,
                  const float* __restrict__ gamma,
                  const float* __restrict__ beta,
                  float* __restrict__ C,
                  int M, int N, int K, int KS) {
    __shared__ float As[16][68];    // [kk][m]
    __shared__ float Bs[16][128];   // [kk][n]
    __shared__ float Fsc[64], Fsh[64];
    int bm = blockIdx.x * 64, bn = blockIdx.y * 128;
    int zi = blockIdx.z;
    int kbeg = zi * KS;
    int tid = threadIdx.x;
    if (tid < 64) {
        float mean = st[tid] * (1.f / BN_COUNT);
        float var = st[64 + tid] * (1.f / BN_COUNT) - mean * mean;
        float inv = rsqrtf(var + EPS);
        float sc = gamma[tid] * inv;
        Fsc[tid] = sc;
        Fsh[tid] = beta[tid] - mean * sc;
    }
    __syncthreads();
    int mt = tid >> 4, nt = tid & 15;
    int m8 = mt * 8, n4 = nt * 4;
    ull acc[8][4];
#pragma unroll
    for (int i = 0; i < 8; i++)
#pragma unroll
        for (int j = 0; j < 4; j++) acc[i][j] = 0ull;

    for (int k0 = kbeg; k0 < kbeg + KS; k0 += 16) {
#pragma unroll
        for (int t = 0; t < 2; t++) {
            int fi = tid + t * 128;            // 0..255 float4 in 64x16 A tile
            int r = fi >> 2, c4 = (fi & 3) * 4;
            float4 v = *(const float4*)&A[(size_t)(bm + r) * K + k0 + c4];
            int ch = (k0 + c4) >> 6;
            float sc = Fsc[ch], sh = Fsh[ch];
            As[c4 + 0][r] = fmaxf(fmaf(v.x, sc, sh), 0.f);
            As[c4 + 1][r] = fmaxf(fmaf(v.y, sc, sh), 0.f);
            As[c4 + 2][r] = fmaxf(fmaf(v.z, sc, sh), 0.f);
            As[c4 + 3][r] = fmaxf(fmaf(v.w, sc, sh), 0.f);
        }
#pragma unroll
        for (int t = 0; t < 4; t++) {
            int fi = tid + t * 128;            // 0..511 float4 in 16x128 B tile
            int r = fi >> 5, c = (fi & 31) * 4;
            *(float4*)&Bs[r][c] = *(const float4*)&W[(size_t)(k0 + r) * N + bn + c];
        }
        __syncthreads();
#pragma unroll
        for (int kk = 0; kk < 16; kk++) {
            F4U a0; a0.f = *(const float4*)&As[kk][m8];
            F4U a1; a1.f = *(const float4*)&As[kk][m8 + 4];
            F4U b0; b0.f = *(const float4*)&Bs[kk][n4];
            F4U b1; b1.f = *(const float4*)&Bs[kk][n4 + 64];
            float am[8] = {a0.s[0], a0.s[1], a0.s[2], a0.s[3],
                           a1.s[0], a1.s[1], a1.s[2], a1.s[3]};
#pragma unroll
            for (int i = 0; i < 8; i++) {
                ull as_ = splat2(am[i]);
                acc[i][0] = fma2(as_, b0.u[0], acc[i][0]);
                acc[i][1] = fma2(as_, b0.u[1], acc[i][1]);
                acc[i][2] = fma2(as_, b1.u[0], acc[i][2]);
                acc[i][3] = fma2(as_, b1.u[1], acc[i][3]);
            }
        }
        __syncthreads();
    }
    float* Co = C + (size_t)zi * M * N;
#pragma unroll
    for (int i = 0; i < 8; i++) {
        F4U c0, c1;
        c0.u[0] = acc[i][0]; c0.u[1] = acc[i][1];
        c1.u[0] = acc[i][2]; c1.u[1] = acc[i][3];
        float* row = &Co[(size_t)(bm + m8 + i) * N + bn];
        *(float4*)&row[n4] = c0.f;
        *(float4*)&row[n4 + 64] = c1.f;
    }
}

// Combine 16 K-split partials + bias + relu. 256 blocks x 256 threads x float4.
__global__ void combine16_relu_kernel(const float* __restrict__ p,
                                      const float* __restrict__ bias,
                                      float* __restrict__ out) {
    int i4 = blockIdx.x * 256 + threadIdx.x;
    int e = i4 * 4;
    int n = e & 255;
    float4 acc = *(const float4*)&bias[n];
#pragma unroll
    for (int z = 0; z < 16; z++) {
        float4 v = *(const float4*)&p[(size_t)z * 262144 + e];
        acc.x += v.x; acc.y += v.y; acc.z += v.z; acc.w += v.w;
    }
    acc.x = fmaxf(acc.x, 0.f);
    acc.y = fmaxf(acc.y, 0.f);
    acc.z = fmaxf(acc.z, 0.f);
    acc.w = fmaxf(acc.w, 0.f);
    *(float4*)&out[e] = acc;
}

// ---------------------------------------------------------------------------
// fp32x2 GEMM for the small 256x256 layers (tile 32x64, 4x4 micro).
__global__ void gemm_f2_kernel(const float* __restrict__ A,
                               const float* __restrict__ W,
                               const float* __restrict__ bias,
                               float* __restrict__ C,
                               int M, int N, int K, int relu) {
    __shared__ float As[16][36];
    __shared__ float Bs[16][64];
    int bm = blockIdx.x * 32, bn = blockIdx.y * 64;
    int tid = threadIdx.x;
    int row4 = (tid >> 4) * 4;
    int col4 = (tid & 15) * 4;
    ull acc[4][2];
    {
        F4U b; b.f = *(const float4*)&bias[bn + col4];
#pragma unroll
        for (int i = 0; i < 4; i++) { acc[i][0] = b.u[0]; acc[i][1] = b.u[1]; }
    }
    for (int k0 = 0; k0 < K; k0 += 16) {
#pragma unroll
        for (int t = 0; t < 4; t++) {
            int idx = tid + t * 128;
            int r = idx >> 4, kk = idx & 15;
            As[kk][r] = A[(bm + r) * K + k0 + kk];
        }
#pragma unroll
        for (int t = 0; t < 8; t++) {
            int idx = tid + t * 128;
            int r = idx >> 6, n = idx & 63;
            Bs[r][n] = W[(k0 + r) * N + bn + n];
        }
        __syncthreads();
#pragma unroll
        for (int kk = 0; kk < 16; kk++) {
            F4U bv; bv.f = *(const float4*)&Bs[kk][col4];
            float4 av = *(const float4*)&As[kk][row4];
            float as_[4] = {av.x, av.y, av.z, av.w};
#pragma unroll
            for (int i = 0; i < 4; i++) {
                ull a = splat2(as_[i]);
                acc[i][0] = fma2(a, bv.u[0], acc[i][0]);
                acc[i][1] = fma2(a, bv.u[1], acc[i][1]);
            }
        }
        __syncthreads();
    }
#pragma unroll
    for (int i = 0; i < 4; i++) {
        F4U c;
        c.u[0] = acc[i][0]; c.u[1] = acc[i][1];
        if (relu) {
            c.s[0] = fmaxf(c.s[0], 0.f);
            c.s[1] = fmaxf(c.s[1], 0.f);
            c.s[2] = fmaxf(c.s[2], 0.f);
            c.s[3] = fmaxf(c.s[3], 0.f);
        }
        *(float4*)&C[(bm + row4 + i) * N + bn + col4] = c.f;
    }
}

// ---------------------------------------------------------------------------
__global__ void head_kernel(const float* __restrict__ act,
                            const float* __restrict__ wp,
                            const float* __restrict__ bp,
                            float* __restrict__ out) {
    __shared__ float sl[256];
    int tid = threadIdx.x;
    int g = blockIdx.x * 16 + (tid >> 4);
    int a = tid & 15;
    const float* ar = act + g * 256;
    float acc = bp[a];
#pragma unroll 8
    for (int k = 0; k < 256; k++) acc = fmaf(ar[k], wp[k * 16 + a], acc);
    sl[tid] = acc;
    __syncthreads();
    int base = tid & ~15;
    float m = -1e30f;
#pragma unroll
    for (int j = 0; j < 16; j++) m = fmaxf(m, sl[base + j]);
    float s = 0.f;
#pragma unroll
    for (int j = 0; j < 16; j++) s += expf(sl[base + j] - m);
    out[g * 16 + a] = acc - m - logf(s);
}

// ---------------------------------------------------------------------------
extern "C" void kernel_launch(void* const* d_in, const int* in_sizes, int n_in,
                              void* d_out, int out_size) {
    const float* x   = (const float*)d_in[0];
    const int*   ei  = (const int*)d_in[1];
    const float* w1  = (const float*)d_in[2];
    const float* b1  = (const float*)d_in[3];
    const float* w2  = (const float*)d_in[4];
    const float* b2  = (const float*)d_in[5];
    const float* c2w = (const float*)d_in[6];
    const float* c2b = (const float*)d_in[7];
    const float* c3w = (const float*)d_in[8];
    const float* c3b = (const float*)d_in[9];
    const float* g1  = (const float*)d_in[10];
    const float* be1 = (const float*)d_in[11];
    const float* g2  = (const float*)d_in[12];
    const float* be2 = (const float*)d_in[13];
    const float* g3  = (const float*)d_in[14];
    const float* be3 = (const float*)d_in[15];
    const float* wm1 = (const float*)d_in[16];
    const float* bm1 = (const float*)d_in[17];
    const float* wm2 = (const float*)d_in[18];
    const float* bm2 = (const float*)d_in[19];
    const float* wm3 = (const float*)d_in[20];
    const float* bm3 = (const float*)d_in[21];
    const float* wp  = (const float*)d_in[22];
    const float* bp  = (const float*)d_in[23];
    float* out = (float*)d_out;

    float *buf1, *buf2, *act1, *act2, *st, *wt;
    cudaGetSymbolAddress((void**)&buf1, g_buf1);
    cudaGetSymbolAddress((void**)&buf2, g_buf2);
    cudaGetSymbolAddress((void**)&act1, g_act1);
    cudaGetSymbolAddress((void**)&act2, g_act2);
    cudaGetSymbolAddress((void**)&st, g_stats);
    cudaGetSymbolAddress((void**)&wt, g_wt);

    cudaFuncSetAttribute(conv8_kernel<true>,
                         cudaFuncAttributeMaxDynamicSharedMemorySize, CONV_SMEM);
    cudaFuncSetAttribute(conv8_kernel<false>,
                         cudaFuncAttributeMaxDynamicSharedMemorySize, CONV_SMEM);

    prep_wt_kernel<<<96, 256>>>(c2w, c3w, wt, st);
    edgeconv_kernel<<<NGRAPH, 256>>>(x, ei, w1, b1, w2, b2, buf1, st);
    conv8_kernel<true><<<512, 256, CONV_SMEM>>>(buf1, st, g1, be1, wt, c2b, buf2, st + 128);
    conv8_kernel<false><<<512, 256, CONV_SMEM>>>(buf2, st + 128, g2, be2, wt + 12288, c3b, buf1, st + 256);
    gemm8_kernel<<<dim3(16, 2, 16), 128>>>(buf1, wm1, st + 256, g3, be3, buf2, 1024, 256, 4096, 256);
    combine16_relu_kernel<<<256, 256>>>(buf2, bm1, act1);
    gemm_f2_kernel<<<dim3(32, 4), 128>>>(act1, wm2, bm2, act2, 1024, 256, 256, 1);
    gemm_f2_kernel<<<dim3(32, 4), 128>>>(act2, wm3, bm3, act1, 1024, 256, 256, 1);
    head_kernel<<<64, 256>>>(act1, wp, bp, out);
}